// round 10
// baseline (speedup 1.0000x reference)
#include <cuda_runtime.h>
#include <cstdint>

#define N_MAX 100000
#define E_MAX 1600000
#define SCAN_BS 1024
#define MAX_BLOCKS 128

// Scratch (no allocations allowed)
__device__ float g_h[(size_t)N_MAX * 64];     // h1 (N x 64), later h3 (N x 2)
__device__ float g_h2[(size_t)N_MAX * 32];    // h2 (N x 32)
__device__ float g_dinv[N_MAX];
__device__ int   g_deg[N_MAX];
__device__ int   g_rowptr[N_MAX + 1];
__device__ int   g_cursor[N_MAX];
__device__ int2  g_edge[E_MAX];               // {src_col, norm_as_float}
__device__ int   g_bsum[MAX_BLOCKS];

static inline int cdiv(long long a, int b) { return (int)((a + b - 1) / b); }

// ---------------------------------------------------------------- degree
__global__ void deg_count_k(const int* __restrict__ dst, int E) {
    int e = blockIdx.x * blockDim.x + threadIdx.x;
    if (e < E) atomicAdd(&g_deg[dst[e]], 1);
}

// ---------------------------------------------------------------- CSR build
__global__ void scan_block_k(int n) {
    __shared__ int sh[SCAN_BS];
    int i = blockIdx.x * SCAN_BS + threadIdx.x;
    int v = (i < n) ? g_deg[i] : 0;
    if (i < n) g_dinv[i] = rsqrtf((float)(v + 1));  // +1 self-loop
    sh[threadIdx.x] = v;
    __syncthreads();
    for (int off = 1; off < SCAN_BS; off <<= 1) {
        int t = (threadIdx.x >= off) ? sh[threadIdx.x - off] : 0;
        __syncthreads();
        sh[threadIdx.x] += t;
        __syncthreads();
    }
    if (i < n) g_rowptr[i] = sh[threadIdx.x] - v;  // exclusive within block
    if (threadIdx.x == SCAN_BS - 1) g_bsum[blockIdx.x] = sh[SCAN_BS - 1];
}

__global__ void scan_sums_k(int nb) {
    int t = threadIdx.x;  // 128 threads
    int lane = t & 31, w = t >> 5;
    int v = (t < nb) ? g_bsum[t] : 0;
    int s = v;
#pragma unroll
    for (int off = 1; off < 32; off <<= 1) {
        int u = __shfl_up_sync(0xffffffffu, s, off);
        if (lane >= off) s += u;
    }
    __shared__ int wsum[4];
    if (lane == 31) wsum[w] = s;
    __syncthreads();
    int base = 0;
    for (int i = 0; i < w; i++) base += wsum[i];
    if (t < nb) g_bsum[t] = base + s - v;  // exclusive
}

__global__ void add_off_k(int n, int E) {
    int i = blockIdx.x * SCAN_BS + threadIdx.x;
    if (i < n) g_rowptr[i] += g_bsum[blockIdx.x];
    if (i == 0) g_rowptr[n] = E;
}

__global__ void place_k(const int* __restrict__ src, const int* __restrict__ dst, int E) {
    int e = blockIdx.x * blockDim.x + threadIdx.x;
    if (e >= E) return;
    int s = src[e], d = dst[e];
    int pos = g_rowptr[d] + atomicAdd(&g_cursor[d], 1);
    int2 pk;
    pk.x = s;
    pk.y = __float_as_int(g_dinv[s] * g_dinv[d]);
    g_edge[pos] = pk;
}

// ---------------------------------------------------------------- layer-1 GEMM
// h1 = x @ W1 (64->64). 2 warps/node, W column in 64 regs, x broadcast by shfl.
__global__ __launch_bounds__(256) void gemm64x64_k(
    const float* __restrict__ x, const float* __restrict__ W,
    float* __restrict__ h, int n) {
    int w = threadIdx.x >> 5, lane = threadIdx.x & 31;
    int col = (w & 1) * 32 + lane;

    float wr[64];
#pragma unroll
    for (int k = 0; k < 64; k++) wr[k] = __ldg(&W[k * 64 + col]);

    int base = blockIdx.x * 32;
#pragma unroll 1
    for (int it = 0; it < 8; it++) {
        int node = base + it * 4 + (w >> 1);
        if (node >= n) return;
        float2 xv = *reinterpret_cast<const float2*>(x + (size_t)node * 64 + lane * 2);
        float acc = 0.0f;
#pragma unroll
        for (int j = 0; j < 32; j++) {
            float xx = __shfl_sync(0xffffffffu, xv.x, j);
            float xy = __shfl_sync(0xffffffffu, xv.y, j);
            acc += xx * wr[2 * j] + xy * wr[2 * j + 1];
        }
        h[(size_t)node * 64 + col] = acc;
    }
}

// ------------------------------------------- fused: agg(h1)+b1, relu, @W2 -> h2
// Warp per node (8 nodes sequentially). Lane owns features (2*lane, 2*lane+1)
// as a float2 accumulator -> 1 LDG.64 per edge gather, then shuffle-GEMM.
__global__ __launch_bounds__(256) void agg64_mm32_k(
    const float* __restrict__ h, const float* __restrict__ b1,
    const float* __restrict__ W2, float* __restrict__ h2, int n) {
    int w = threadIdx.x >> 5, lane = threadIdx.x & 31;

    float wr[64];
#pragma unroll
    for (int k = 0; k < 64; k++) wr[k] = __ldg(&W2[k * 32 + lane]);
    float2 bb = *reinterpret_cast<const float2*>(b1 + lane * 2);

    int base = blockIdx.x * 64 + w * 8;
#pragma unroll 1
    for (int it = 0; it < 8; it++) {
        int node = base + it;
        if (node >= n) return;
        float di = g_dinv[node];
        float sl = di * di;
        float2 hv = *reinterpret_cast<const float2*>(h + (size_t)node * 64 + lane * 2);
        float a0 = sl * hv.x + bb.x;
        float a1 = sl * hv.y + bb.y;

        int beg = g_rowptr[node], end = g_rowptr[node + 1];
        int e = beg;
        for (; e + 3 < end; e += 4) {
            int2 e0 = g_edge[e],     e1 = g_edge[e + 1];
            int2 e2 = g_edge[e + 2], e3 = g_edge[e + 3];
            float2 v0 = *reinterpret_cast<const float2*>(h + (size_t)e0.x * 64 + lane * 2);
            float2 v1 = *reinterpret_cast<const float2*>(h + (size_t)e1.x * 64 + lane * 2);
            float2 v2 = *reinterpret_cast<const float2*>(h + (size_t)e2.x * 64 + lane * 2);
            float2 v3 = *reinterpret_cast<const float2*>(h + (size_t)e3.x * 64 + lane * 2);
            float w0 = __int_as_float(e0.y), w1 = __int_as_float(e1.y);
            float w2f = __int_as_float(e2.y), w3f = __int_as_float(e3.y);
            a0 += w0 * v0.x + w1 * v1.x + w2f * v2.x + w3f * v3.x;
            a1 += w0 * v0.y + w1 * v1.y + w2f * v2.y + w3f * v3.y;
        }
        for (; e < end; e++) {
            int2 e0 = g_edge[e];
            float2 v0 = *reinterpret_cast<const float2*>(h + (size_t)e0.x * 64 + lane * 2);
            float w0 = __int_as_float(e0.y);
            a0 += w0 * v0.x;
            a1 += w0 * v0.y;
        }

        // relu + GEMM 64->32 via shuffle broadcast
        a0 = fmaxf(a0, 0.0f);
        a1 = fmaxf(a1, 0.0f);
        float acc = 0.0f;
#pragma unroll
        for (int j = 0; j < 32; j++) {
            float xx = __shfl_sync(0xffffffffu, a0, j);
            float xy = __shfl_sync(0xffffffffu, a1, j);
            acc += xx * wr[2 * j] + xy * wr[2 * j + 1];
        }
        h2[(size_t)node * 32 + lane] = acc;
    }
}

// ------------------------------------------- fused: agg(h2)+b2, relu, @W3 -> h3
// Warp per node (8 sequential). Lane owns feature `lane`; epilogue butterfly.
__global__ __launch_bounds__(256) void agg32_mm2_k(
    const float* __restrict__ h2, const float* __restrict__ b2,
    const float* __restrict__ W3, float* __restrict__ h3, int n) {
    int w = threadIdx.x >> 5, lane = threadIdx.x & 31;
    float w30 = __ldg(&W3[lane * 2 + 0]);
    float w31 = __ldg(&W3[lane * 2 + 1]);
    float bb = __ldg(&b2[lane]);

    int base = blockIdx.x * 64 + w * 8;
#pragma unroll 1
    for (int it = 0; it < 8; it++) {
        int node = base + it;
        if (node >= n) return;
        float di = g_dinv[node];
        float a0 = di * di * h2[(size_t)node * 32 + lane] + bb;

        int beg = g_rowptr[node], end = g_rowptr[node + 1];
        int e = beg;
        for (; e + 3 < end; e += 4) {
            int2 e0 = g_edge[e],     e1 = g_edge[e + 1];
            int2 e2 = g_edge[e + 2], e3 = g_edge[e + 3];
            float v0 = h2[(size_t)e0.x * 32 + lane];
            float v1 = h2[(size_t)e1.x * 32 + lane];
            float v2 = h2[(size_t)e2.x * 32 + lane];
            float v3 = h2[(size_t)e3.x * 32 + lane];
            a0 += __int_as_float(e0.y) * v0 + __int_as_float(e1.y) * v1
                + __int_as_float(e2.y) * v2 + __int_as_float(e3.y) * v3;
        }
        for (; e < end; e++) {
            int2 e0 = g_edge[e];
            a0 += __int_as_float(e0.y) * h2[(size_t)e0.x * 32 + lane];
        }

        // relu + GEMM 32->2
        a0 = fmaxf(a0, 0.0f);
        float p0 = a0 * w30;
        float p1 = a0 * w31;
#pragma unroll
        for (int off = 16; off; off >>= 1) {
            p0 += __shfl_xor_sync(0xffffffffu, p0, off);
            p1 += __shfl_xor_sync(0xffffffffu, p1, off);
        }
        if (lane == 0) {
            h3[(size_t)node * 2 + 0] = p0;
            h3[(size_t)node * 2 + 1] = p1;
        }
    }
}

// ------------------------------------------- final aggregation over 2-dim rows
__global__ void aggregate2_k(const float* __restrict__ h, const float* __restrict__ b,
                             float* __restrict__ agg, int n) {
    int node = (blockIdx.x * blockDim.x + threadIdx.x) >> 5;
    int lane = threadIdx.x & 31;
    if (node >= n) return;
    int beg = g_rowptr[node], end = g_rowptr[node + 1];
    float ax = 0.0f, ay = 0.0f;
    for (int e = beg + lane; e < end; e += 32) {
        int2 e0 = g_edge[e];
        float w = __int_as_float(e0.y);
        float2 hv = *reinterpret_cast<const float2*>(h + (size_t)e0.x * 2);
        ax += w * hv.x;
        ay += w * hv.y;
    }
#pragma unroll
    for (int off = 16; off; off >>= 1) {
        ax += __shfl_xor_sync(0xffffffffu, ax, off);
        ay += __shfl_xor_sync(0xffffffffu, ay, off);
    }
    if (lane == 0) {
        float di = g_dinv[node], sl = di * di;
        float2 hv = *reinterpret_cast<const float2*>(h + (size_t)node * 2);
        agg[(size_t)node * 2 + 0] = ax + sl * hv.x + b[0];
        agg[(size_t)node * 2 + 1] = ay + sl * hv.y + b[1];
    }
}

extern "C" void kernel_launch(void* const* d_in, const int* in_sizes, int n_in,
                              void* d_out, int out_size) {
    const float* x  = (const float*)d_in[0];
    const int*   ei = (const int*)d_in[1];
    const float* W1 = (const float*)d_in[2];
    const float* b1 = (const float*)d_in[3];
    const float* W2 = (const float*)d_in[4];
    const float* b2 = (const float*)d_in[5];
    const float* W3 = (const float*)d_in[6];
    const float* b3 = (const float*)d_in[7];
    float* out = (float*)d_out;

    int n = in_sizes[0] / 64;   // 100000
    int E = in_sizes[1] / 2;    // 1600000
    const int* src = ei;
    const int* dst = ei + E;

    float *ph, *ph2;
    void *pdeg, *pcur;
    cudaGetSymbolAddress((void**)&ph, g_h);
    cudaGetSymbolAddress((void**)&ph2, g_h2);
    cudaGetSymbolAddress(&pdeg, g_deg);
    cudaGetSymbolAddress(&pcur, g_cursor);

    int nb = cdiv(n, SCAN_BS);

    // ---- CSR build + norms
    cudaMemsetAsync(pdeg, 0, n * sizeof(int));
    cudaMemsetAsync(pcur, 0, n * sizeof(int));
    deg_count_k<<<cdiv(E, 256), 256>>>(dst, E);
    scan_block_k<<<nb, SCAN_BS>>>(n);      // also computes dinv
    scan_sums_k<<<1, 128>>>(nb);
    add_off_k<<<nb, SCAN_BS>>>(n, E);
    place_k<<<cdiv(E, 256), 256>>>(src, dst, E);

    // ---- layer 1: h1 = x @ W1
    gemm64x64_k<<<cdiv(n, 32), 256>>>(x, W1, ph, n);

    // ---- fused layer-1 agg + relu + layer-2 GEMM -> h2
    agg64_mm32_k<<<cdiv(n, 64), 256>>>(ph, b1, W2, ph2, n);

    // ---- fused layer-2 agg + relu + layer-3 GEMM -> h3 (reuse g_h)
    agg32_mm2_k<<<cdiv(n, 64), 256>>>(ph2, b2, W3, ph, n);

    // ---- final aggregation -> out
    aggregate2_k<<<cdiv((long long)n * 32, 256), 256>>>(ph, b3, out, n);
}

// round 12
// speedup vs baseline: 1.2162x; 1.2162x over previous
#include <cuda_runtime.h>
#include <cstdint>

#define N_MAX 100000
#define E_MAX 1600000
#define SCAN_BS 1024
#define MAX_BLOCKS 128

// Scratch (no allocations allowed)
__device__ float g_h[(size_t)N_MAX * 64];    // h1; later reused as h2 (N x 32)
__device__ float g_agg[(size_t)N_MAX * 64];  // a1; later reused as h3 (N x 2)
__device__ float g_dinv[N_MAX];
__device__ int   g_deg[N_MAX];
__device__ int   g_rowptr[N_MAX + 1];
__device__ int   g_cursor[N_MAX];
__device__ int2  g_edge[E_MAX];              // {src_col, norm_as_float}
__device__ int   g_bsum[MAX_BLOCKS];

static inline int cdiv(long long a, int b) { return (int)((a + b - 1) / b); }

// ---------------------------------------------------------------- degree
__global__ void deg_count_k(const int* __restrict__ dst, int E) {
    int e = blockIdx.x * blockDim.x + threadIdx.x;
    if (e < E) atomicAdd(&g_deg[dst[e]], 1);
}

// ---------------------------------------------------------------- CSR build
__global__ void scan_block_k(int n) {
    __shared__ int sh[SCAN_BS];
    int i = blockIdx.x * SCAN_BS + threadIdx.x;
    int v = (i < n) ? g_deg[i] : 0;
    if (i < n) g_dinv[i] = rsqrtf((float)(v + 1));  // +1 self-loop
    sh[threadIdx.x] = v;
    __syncthreads();
    for (int off = 1; off < SCAN_BS; off <<= 1) {
        int t = (threadIdx.x >= off) ? sh[threadIdx.x - off] : 0;
        __syncthreads();
        sh[threadIdx.x] += t;
        __syncthreads();
    }
    if (i < n) g_rowptr[i] = sh[threadIdx.x] - v;  // exclusive within block
    if (threadIdx.x == SCAN_BS - 1) g_bsum[blockIdx.x] = sh[SCAN_BS - 1];
}

__global__ void scan_sums_k(int nb) {
    int t = threadIdx.x;  // 128 threads
    int lane = t & 31, w = t >> 5;
    int v = (t < nb) ? g_bsum[t] : 0;
    int s = v;
#pragma unroll
    for (int off = 1; off < 32; off <<= 1) {
        int u = __shfl_up_sync(0xffffffffu, s, off);
        if (lane >= off) s += u;
    }
    __shared__ int wsum[4];
    if (lane == 31) wsum[w] = s;
    __syncthreads();
    int base = 0;
    for (int i = 0; i < w; i++) base += wsum[i];
    if (t < nb) g_bsum[t] = base + s - v;  // exclusive
}

__global__ void add_off_k(int n, int E) {
    int i = blockIdx.x * SCAN_BS + threadIdx.x;
    if (i < n) g_rowptr[i] += g_bsum[blockIdx.x];
    if (i == 0) g_rowptr[n] = E;
}

__global__ void place_k(const int* __restrict__ src, const int* __restrict__ dst, int E) {
    int e = blockIdx.x * blockDim.x + threadIdx.x;
    if (e >= E) return;
    int s = src[e], d = dst[e];
    int pos = g_rowptr[d] + atomicAdd(&g_cursor[d], 1);
    int2 pk;
    pk.x = s;
    pk.y = __float_as_int(g_dinv[s] * g_dinv[d]);
    g_edge[pos] = pk;
}

// ---------------------------------------------------------------- layer-1 GEMM
// h1 = x @ W1 (64->64). 2 warps/node, W column in 64 regs, x broadcast by shfl.
__global__ __launch_bounds__(256) void gemm64x64_k(
    const float* __restrict__ x, const float* __restrict__ W,
    float* __restrict__ h, int n) {
    int w = threadIdx.x >> 5, lane = threadIdx.x & 31;
    int col = (w & 1) * 32 + lane;

    float wr[64];
#pragma unroll
    for (int k = 0; k < 64; k++) wr[k] = __ldg(&W[k * 64 + col]);

    int base = blockIdx.x * 32;
#pragma unroll 1
    for (int it = 0; it < 8; it++) {
        int node = base + it * 4 + (w >> 1);
        if (node >= n) return;
        float2 xv = *reinterpret_cast<const float2*>(x + (size_t)node * 64 + lane * 2);
        float acc = 0.0f;
#pragma unroll
        for (int j = 0; j < 32; j++) {
            float xx = __shfl_sync(0xffffffffu, xv.x, j);
            float xy = __shfl_sync(0xffffffffu, xv.y, j);
            acc += xx * wr[2 * j] + xy * wr[2 * j + 1];
        }
        h[(size_t)node * 64 + col] = acc;
    }
}

// ------------------------------------------------ aggregation (64 features)
// Warp per node, lane owns features (2*lane, 2*lane+1) -> 1 LDG.64 per edge.
// Lean (low regs) so occupancy hides the L2 gather latency. 4-edge unroll.
__global__ void aggregate64_k(const float* __restrict__ h, const float* __restrict__ b,
                              float* __restrict__ agg, int n) {
    int node = (blockIdx.x * blockDim.x + threadIdx.x) >> 5;
    int lane = threadIdx.x & 31;
    if (node >= n) return;
    float di = g_dinv[node];
    float sl = di * di;
    float2 hv = *reinterpret_cast<const float2*>(h + (size_t)node * 64 + lane * 2);
    float2 bb = *reinterpret_cast<const float2*>(b + lane * 2);
    float a0 = sl * hv.x + bb.x;
    float a1 = sl * hv.y + bb.y;

    int beg = g_rowptr[node], end = g_rowptr[node + 1];
    int e = beg;
    for (; e + 3 < end; e += 4) {
        int2 e0 = g_edge[e],     e1 = g_edge[e + 1];
        int2 e2 = g_edge[e + 2], e3 = g_edge[e + 3];
        float2 v0 = *reinterpret_cast<const float2*>(h + (size_t)e0.x * 64 + lane * 2);
        float2 v1 = *reinterpret_cast<const float2*>(h + (size_t)e1.x * 64 + lane * 2);
        float2 v2 = *reinterpret_cast<const float2*>(h + (size_t)e2.x * 64 + lane * 2);
        float2 v3 = *reinterpret_cast<const float2*>(h + (size_t)e3.x * 64 + lane * 2);
        float w0 = __int_as_float(e0.y), w1 = __int_as_float(e1.y);
        float w2 = __int_as_float(e2.y), w3 = __int_as_float(e3.y);
        a0 += w0 * v0.x + w1 * v1.x + w2 * v2.x + w3 * v3.x;
        a1 += w0 * v0.y + w1 * v1.y + w2 * v2.y + w3 * v3.y;
    }
    for (; e < end; e++) {
        int2 e0 = g_edge[e];
        float2 v0 = *reinterpret_cast<const float2*>(h + (size_t)e0.x * 64 + lane * 2);
        float w0 = __int_as_float(e0.y);
        a0 += w0 * v0.x;
        a1 += w0 * v0.y;
    }
    float2 o; o.x = a0; o.y = a1;
    *reinterpret_cast<float2*>(agg + (size_t)node * 64 + lane * 2) = o;
}

// ---------------------------------------------------------------- layer-2 GEMM
// h2 = relu(a1) @ W2 (64->32). 1 warp/node, 8 nodes sequential; a1 rows are in
// pair layout (lane owns 2*lane, 2*lane+1) matching aggregate64 output.
__global__ __launch_bounds__(256) void gemm64x32_k(
    const float* __restrict__ x, const float* __restrict__ W,
    float* __restrict__ h, int n) {
    int w = threadIdx.x >> 5, lane = threadIdx.x & 31;

    float wr[64];
#pragma unroll
    for (int k = 0; k < 64; k++) wr[k] = __ldg(&W[k * 32 + lane]);

    int base = blockIdx.x * 64;
#pragma unroll 1
    for (int it = 0; it < 8; it++) {
        int node = base + it * 8 + w;
        if (node >= n) return;
        float2 xv = *reinterpret_cast<const float2*>(x + (size_t)node * 64 + lane * 2);
        xv.x = fmaxf(xv.x, 0.0f);
        xv.y = fmaxf(xv.y, 0.0f);
        float acc = 0.0f;
#pragma unroll
        for (int j = 0; j < 32; j++) {
            float xx = __shfl_sync(0xffffffffu, xv.x, j);
            float xy = __shfl_sync(0xffffffffu, xv.y, j);
            acc += xx * wr[2 * j] + xy * wr[2 * j + 1];
        }
        h[(size_t)node * 32 + lane] = acc;
    }
}

// --------------------------- fused: agg(h2)+b2, relu, @W3 -> h3 (warp per node)
// Adds only ~4 regs over the plain aggregation -> occupancy preserved.
__global__ void agg32_mm2_k(const float* __restrict__ h2, const float* __restrict__ b2,
                            const float* __restrict__ W3, float* __restrict__ h3, int n) {
    int node = (blockIdx.x * blockDim.x + threadIdx.x) >> 5;
    int lane = threadIdx.x & 31;
    if (node >= n) return;
    float di = g_dinv[node];
    float a0 = di * di * h2[(size_t)node * 32 + lane] + __ldg(&b2[lane]);

    int beg = g_rowptr[node], end = g_rowptr[node + 1];
    int e = beg;
    for (; e + 3 < end; e += 4) {
        int2 e0 = g_edge[e],     e1 = g_edge[e + 1];
        int2 e2 = g_edge[e + 2], e3 = g_edge[e + 3];
        float v0 = h2[(size_t)e0.x * 32 + lane];
        float v1 = h2[(size_t)e1.x * 32 + lane];
        float v2 = h2[(size_t)e2.x * 32 + lane];
        float v3 = h2[(size_t)e3.x * 32 + lane];
        a0 += __int_as_float(e0.y) * v0 + __int_as_float(e1.y) * v1
            + __int_as_float(e2.y) * v2 + __int_as_float(e3.y) * v3;
    }
    for (; e < end; e++) {
        int2 e0 = g_edge[e];
        a0 += __int_as_float(e0.y) * h2[(size_t)e0.x * 32 + lane];
    }

    // relu + GEMM 32->2
    a0 = fmaxf(a0, 0.0f);
    float p0 = a0 * __ldg(&W3[lane * 2 + 0]);
    float p1 = a0 * __ldg(&W3[lane * 2 + 1]);
#pragma unroll
    for (int off = 16; off; off >>= 1) {
        p0 += __shfl_xor_sync(0xffffffffu, p0, off);
        p1 += __shfl_xor_sync(0xffffffffu, p1, off);
    }
    if (lane == 0) {
        float2 o; o.x = p0; o.y = p1;
        *reinterpret_cast<float2*>(h3 + (size_t)node * 2) = o;
    }
}

// ------------------------------------------- final aggregation over 2-dim rows
__global__ void aggregate2_k(const float* __restrict__ h, const float* __restrict__ b,
                             float* __restrict__ agg, int n) {
    int node = (blockIdx.x * blockDim.x + threadIdx.x) >> 5;
    int lane = threadIdx.x & 31;
    if (node >= n) return;
    int beg = g_rowptr[node], end = g_rowptr[node + 1];
    float ax = 0.0f, ay = 0.0f;
    for (int e = beg + lane; e < end; e += 32) {
        int2 e0 = g_edge[e];
        float w = __int_as_float(e0.y);
        float2 hv = *reinterpret_cast<const float2*>(h + (size_t)e0.x * 2);
        ax += w * hv.x;
        ay += w * hv.y;
    }
#pragma unroll
    for (int off = 16; off; off >>= 1) {
        ax += __shfl_xor_sync(0xffffffffu, ax, off);
        ay += __shfl_xor_sync(0xffffffffu, ay, off);
    }
    if (lane == 0) {
        float di = g_dinv[node], sl = di * di;
        float2 hv = *reinterpret_cast<const float2*>(h + (size_t)node * 2);
        agg[(size_t)node * 2 + 0] = ax + sl * hv.x + b[0];
        agg[(size_t)node * 2 + 1] = ay + sl * hv.y + b[1];
    }
}

extern "C" void kernel_launch(void* const* d_in, const int* in_sizes, int n_in,
                              void* d_out, int out_size) {
    const float* x  = (const float*)d_in[0];
    const int*   ei = (const int*)d_in[1];
    const float* W1 = (const float*)d_in[2];
    const float* b1 = (const float*)d_in[3];
    const float* W2 = (const float*)d_in[4];
    const float* b2 = (const float*)d_in[5];
    const float* W3 = (const float*)d_in[6];
    const float* b3 = (const float*)d_in[7];
    float* out = (float*)d_out;

    int n = in_sizes[0] / 64;   // 100000
    int E = in_sizes[1] / 2;    // 1600000
    const int* src = ei;
    const int* dst = ei + E;

    float *ph, *pagg;
    void *pdeg, *pcur;
    cudaGetSymbolAddress((void**)&ph, g_h);
    cudaGetSymbolAddress((void**)&pagg, g_agg);
    cudaGetSymbolAddress(&pdeg, g_deg);
    cudaGetSymbolAddress(&pcur, g_cursor);

    int nb = cdiv(n, SCAN_BS);

    // ---- CSR build + norms
    cudaMemsetAsync(pdeg, 0, n * sizeof(int));
    cudaMemsetAsync(pcur, 0, n * sizeof(int));
    deg_count_k<<<cdiv(E, 256), 256>>>(dst, E);
    scan_block_k<<<nb, SCAN_BS>>>(n);      // also computes dinv
    scan_sums_k<<<1, 128>>>(nb);
    add_off_k<<<nb, SCAN_BS>>>(n, E);
    place_k<<<cdiv(E, 256), 256>>>(src, dst, E);

    // ---- layer 1: h1 = x @ W1 ; a1 = A_hat h1 + b1 (pair layout)
    gemm64x64_k<<<cdiv(n, 32), 256>>>(x, W1, ph, n);
    aggregate64_k<<<cdiv((long long)n * 32, 256), 256>>>(ph, b1, pagg, n);

    // ---- layer 2: h2 = relu(a1) @ W2 (reuse g_h)
    gemm64x32_k<<<cdiv(n, 64), 256>>>(pagg, W2, ph, n);

    // ---- fused layer-2 agg + relu + layer-3 GEMM -> h3 (reuse g_agg)
    agg32_mm2_k<<<cdiv((long long)n * 32, 256), 256>>>(ph, b2, W3, pagg, n);

    // ---- final aggregation -> out
    aggregate2_k<<<cdiv((long long)n * 32, 256), 256>>>(pagg, b3, out, n);
}

// round 13
// speedup vs baseline: 1.2350x; 1.0155x over previous
#include <cuda_runtime.h>
#include <cstdint>

#define N_MAX 100000
#define E_MAX 1600000
#define SCAN_BS 1024

// Scratch (no allocations allowed)
__device__ float g_h[(size_t)N_MAX * 64];    // h1; later reused as h2 (N x 32)
__device__ float g_agg[(size_t)N_MAX * 64];  // a1; later reused as h3 (N x 2)
__device__ float g_dinv[N_MAX];
__device__ int   g_deg[N_MAX];
__device__ int   g_rowptr[N_MAX + 1];
__device__ int   g_cursor[N_MAX];            // running insert ptr (init = rowptr)
__device__ int2  g_edge[E_MAX];              // {src, norm_as_float}
__device__ int   g_bsum[128];

static inline int cdiv(long long a, int b) { return (int)((a + b - 1) / b); }

// ---------------------------------------------------------------- GEMM body
// h[node, col] for 64->64, 2 warps/node, W column in 64 regs, x bcast by shfl.
__device__ __forceinline__ void gemm64x64_body(
    const float* __restrict__ x, const float* __restrict__ W,
    float* __restrict__ h, int n, int blk) {
    int w = threadIdx.x >> 5, lane = threadIdx.x & 31;
    int col = (w & 1) * 32 + lane;

    float wr[64];
#pragma unroll
    for (int k = 0; k < 64; k++) wr[k] = __ldg(&W[k * 64 + col]);

    int base = blk * 32;
#pragma unroll 1
    for (int it = 0; it < 8; it++) {
        int node = base + it * 4 + (w >> 1);
        if (node >= n) return;
        float2 xv = *reinterpret_cast<const float2*>(x + (size_t)node * 64 + lane * 2);
        float acc = 0.0f;
#pragma unroll
        for (int j = 0; j < 32; j++) {
            float xx = __shfl_sync(0xffffffffu, xv.x, j);
            float xy = __shfl_sync(0xffffffffu, xv.y, j);
            acc += xx * wr[2 * j] + xy * wr[2 * j + 1];
        }
        h[(size_t)node * 64 + col] = acc;
    }
}

// ---------------- combined kernel 1: gemm (first chunk) || degree count
__global__ __launch_bounds__(256) void gemm1_deg_k(
    const float* __restrict__ x, const float* __restrict__ W,
    float* __restrict__ h, int n_gemm, int gemm_blocks,
    const int* __restrict__ dst, int E) {
    if ((int)blockIdx.x < gemm_blocks) {
        gemm64x64_body(x, W, h, n_gemm, blockIdx.x);
    } else {
        int e = (blockIdx.x - gemm_blocks) * 256 + threadIdx.x;
        if (e < E) atomicAdd(&g_deg[dst[e]], 1);
    }
}

// ---------------------------------------------------------------- CSR scan
__global__ void scan_block_k(int n) {
    __shared__ int sh[SCAN_BS];
    int i = blockIdx.x * SCAN_BS + threadIdx.x;
    int v = (i < n) ? g_deg[i] : 0;
    if (i < n) g_dinv[i] = rsqrtf((float)(v + 1));  // +1 self-loop
    sh[threadIdx.x] = v;
    __syncthreads();
    for (int off = 1; off < SCAN_BS; off <<= 1) {
        int t = (threadIdx.x >= off) ? sh[threadIdx.x - off] : 0;
        __syncthreads();
        sh[threadIdx.x] += t;
        __syncthreads();
    }
    if (i < n) g_rowptr[i] = sh[threadIdx.x] - v;  // exclusive within block
    if (threadIdx.x == SCAN_BS - 1) g_bsum[blockIdx.x] = sh[SCAN_BS - 1];
}

// add block offsets (each block reduces its own prefix of bsum: <=98 values),
// and initialize cursor = rowptr (so place_k needs no separate memset).
__global__ void add_off_k(int n, int E) {
    __shared__ int sbase;
    if (threadIdx.x < 32) {
        int acc = 0;
        for (int j = threadIdx.x; j < (int)blockIdx.x; j += 32) acc += g_bsum[j];
#pragma unroll
        for (int off = 16; off; off >>= 1) acc += __shfl_xor_sync(0xffffffffu, acc, off);
        if (threadIdx.x == 0) sbase = acc;
    }
    __syncthreads();
    int i = blockIdx.x * SCAN_BS + threadIdx.x;
    if (i < n) {
        int r = g_rowptr[i] + sbase;
        g_rowptr[i] = r;
        g_cursor[i] = r;
    }
    if (i == 0) g_rowptr[n] = E;
}

// ---------------- combined kernel 2: edge placement || gemm (second chunk)
__global__ __launch_bounds__(256) void place_gemm1b_k(
    const int* __restrict__ src, const int* __restrict__ dst, int E, int place_blocks,
    const float* __restrict__ x, const float* __restrict__ W,
    float* __restrict__ h, int n, int node_blk_off) {
    if ((int)blockIdx.x < place_blocks) {
        int e = blockIdx.x * 256 + threadIdx.x;
        if (e >= E) return;
        int s = src[e], d = dst[e];
        int pos = atomicAdd(&g_cursor[d], 1);
        int2 pk;
        pk.x = s;
        pk.y = __float_as_int(g_dinv[s] * g_dinv[d]);
        g_edge[pos] = pk;
    } else {
        gemm64x64_body(x, W, h, n, node_blk_off + (blockIdx.x - place_blocks));
    }
}

// ------------------------------------------------ aggregation (64 features)
// Warp per node, lane owns features (2*lane, 2*lane+1) -> 1 LDG.64 per edge.
__global__ void aggregate64_k(const float* __restrict__ h, const float* __restrict__ b,
                              float* __restrict__ agg, int n) {
    int node = (blockIdx.x * blockDim.x + threadIdx.x) >> 5;
    int lane = threadIdx.x & 31;
    if (node >= n) return;
    float di = g_dinv[node];
    float sl = di * di;
    float2 hv = *reinterpret_cast<const float2*>(h + (size_t)node * 64 + lane * 2);
    float2 bb = *reinterpret_cast<const float2*>(b + lane * 2);
    float a0 = sl * hv.x + bb.x;
    float a1 = sl * hv.y + bb.y;

    int beg = g_rowptr[node], end = g_rowptr[node + 1];
    int e = beg;
    for (; e + 3 < end; e += 4) {
        int2 e0 = g_edge[e],     e1 = g_edge[e + 1];
        int2 e2 = g_edge[e + 2], e3 = g_edge[e + 3];
        float2 v0 = *reinterpret_cast<const float2*>(h + (size_t)e0.x * 64 + lane * 2);
        float2 v1 = *reinterpret_cast<const float2*>(h + (size_t)e1.x * 64 + lane * 2);
        float2 v2 = *reinterpret_cast<const float2*>(h + (size_t)e2.x * 64 + lane * 2);
        float2 v3 = *reinterpret_cast<const float2*>(h + (size_t)e3.x * 64 + lane * 2);
        float w0 = __int_as_float(e0.y), w1 = __int_as_float(e1.y);
        float w2 = __int_as_float(e2.y), w3 = __int_as_float(e3.y);
        a0 += w0 * v0.x + w1 * v1.x + w2 * v2.x + w3 * v3.x;
        a1 += w0 * v0.y + w1 * v1.y + w2 * v2.y + w3 * v3.y;
    }
    for (; e < end; e++) {
        int2 e0 = g_edge[e];
        float2 v0 = *reinterpret_cast<const float2*>(h + (size_t)e0.x * 64 + lane * 2);
        float w0 = __int_as_float(e0.y);
        a0 += w0 * v0.x;
        a1 += w0 * v0.y;
    }
    float2 o; o.x = a0; o.y = a1;
    *reinterpret_cast<float2*>(agg + (size_t)node * 64 + lane * 2) = o;
}

// ---------------------------------------------------------------- layer-2 GEMM
// h2 = relu(a1) @ W2 (64->32). a1 rows in pair layout (lane owns 2l, 2l+1).
__global__ __launch_bounds__(256) void gemm64x32_k(
    const float* __restrict__ x, const float* __restrict__ W,
    float* __restrict__ h, int n) {
    int w = threadIdx.x >> 5, lane = threadIdx.x & 31;

    float wr[64];
#pragma unroll
    for (int k = 0; k < 64; k++) wr[k] = __ldg(&W[k * 32 + lane]);

    int base = blockIdx.x * 64;
#pragma unroll 1
    for (int it = 0; it < 8; it++) {
        int node = base + it * 8 + w;
        if (node >= n) return;
        float2 xv = *reinterpret_cast<const float2*>(x + (size_t)node * 64 + lane * 2);
        xv.x = fmaxf(xv.x, 0.0f);
        xv.y = fmaxf(xv.y, 0.0f);
        float acc = 0.0f;
#pragma unroll
        for (int j = 0; j < 32; j++) {
            float xx = __shfl_sync(0xffffffffu, xv.x, j);
            float xy = __shfl_sync(0xffffffffu, xv.y, j);
            acc += xx * wr[2 * j] + xy * wr[2 * j + 1];
        }
        h[(size_t)node * 32 + lane] = acc;
    }
}

// --------------------------- fused: agg(h2)+b2, relu, @W3 -> h3 (warp per node)
__global__ void agg32_mm2_k(const float* __restrict__ h2, const float* __restrict__ b2,
                            const float* __restrict__ W3, float* __restrict__ h3, int n) {
    int node = (blockIdx.x * blockDim.x + threadIdx.x) >> 5;
    int lane = threadIdx.x & 31;
    if (node >= n) return;
    float di = g_dinv[node];
    float a0 = di * di * h2[(size_t)node * 32 + lane] + __ldg(&b2[lane]);

    int beg = g_rowptr[node], end = g_rowptr[node + 1];
    int e = beg;
    for (; e + 3 < end; e += 4) {
        int2 e0 = g_edge[e],     e1 = g_edge[e + 1];
        int2 e2 = g_edge[e + 2], e3 = g_edge[e + 3];
        float v0 = h2[(size_t)e0.x * 32 + lane];
        float v1 = h2[(size_t)e1.x * 32 + lane];
        float v2 = h2[(size_t)e2.x * 32 + lane];
        float v3 = h2[(size_t)e3.x * 32 + lane];
        a0 += __int_as_float(e0.y) * v0 + __int_as_float(e1.y) * v1
            + __int_as_float(e2.y) * v2 + __int_as_float(e3.y) * v3;
    }
    for (; e < end; e++) {
        int2 e0 = g_edge[e];
        a0 += __int_as_float(e0.y) * h2[(size_t)e0.x * 32 + lane];
    }

    a0 = fmaxf(a0, 0.0f);
    float p0 = a0 * __ldg(&W3[lane * 2 + 0]);
    float p1 = a0 * __ldg(&W3[lane * 2 + 1]);
#pragma unroll
    for (int off = 16; off; off >>= 1) {
        p0 += __shfl_xor_sync(0xffffffffu, p0, off);
        p1 += __shfl_xor_sync(0xffffffffu, p1, off);
    }
    if (lane == 0) {
        float2 o; o.x = p0; o.y = p1;
        *reinterpret_cast<float2*>(h3 + (size_t)node * 2) = o;
    }
}

// ------------------------------------------- final aggregation over 2-dim rows
__global__ void aggregate2_k(const float* __restrict__ h, const float* __restrict__ b,
                             float* __restrict__ agg, int n) {
    int node = (blockIdx.x * blockDim.x + threadIdx.x) >> 5;
    int lane = threadIdx.x & 31;
    if (node >= n) return;
    int beg = g_rowptr[node], end = g_rowptr[node + 1];
    float ax = 0.0f, ay = 0.0f;
    for (int e = beg + lane; e < end; e += 32) {
        int2 e0 = g_edge[e];
        float w = __int_as_float(e0.y);
        float2 hv = *reinterpret_cast<const float2*>(h + (size_t)e0.x * 2);
        ax += w * hv.x;
        ay += w * hv.y;
    }
#pragma unroll
    for (int off = 16; off; off >>= 1) {
        ax += __shfl_xor_sync(0xffffffffu, ax, off);
        ay += __shfl_xor_sync(0xffffffffu, ay, off);
    }
    if (lane == 0) {
        float di = g_dinv[node], sl = di * di;
        float2 hv = *reinterpret_cast<const float2*>(h + (size_t)node * 2);
        agg[(size_t)node * 2 + 0] = ax + sl * hv.x + b[0];
        agg[(size_t)node * 2 + 1] = ay + sl * hv.y + b[1];
    }
}

extern "C" void kernel_launch(void* const* d_in, const int* in_sizes, int n_in,
                              void* d_out, int out_size) {
    const float* x  = (const float*)d_in[0];
    const int*   ei = (const int*)d_in[1];
    const float* W1 = (const float*)d_in[2];
    const float* b1 = (const float*)d_in[3];
    const float* W2 = (const float*)d_in[4];
    const float* b2 = (const float*)d_in[5];
    const float* W3 = (const float*)d_in[6];
    const float* b3 = (const float*)d_in[7];
    float* out = (float*)d_out;

    int n = in_sizes[0] / 64;   // 100000
    int E = in_sizes[1] / 2;    // 1600000
    const int* src = ei;
    const int* dst = ei + E;

    float *ph, *pagg;
    void *pdeg;
    cudaGetSymbolAddress((void**)&ph, g_h);
    cudaGetSymbolAddress((void**)&pagg, g_agg);
    cudaGetSymbolAddress(&pdeg, g_deg);

    int nb = cdiv(n, SCAN_BS);
    int gemm_blocks_total = cdiv(n, 32);
    int gemm_blocks_1 = gemm_blocks_total / 2;               // first chunk with deg
    int gemm_blocks_2 = gemm_blocks_total - gemm_blocks_1;   // second chunk with place
    int deg_blocks = cdiv(E, 256);
    int place_blocks = cdiv(E, 256);

    // deg = 0 (cursor is initialized by add_off_k, no memset needed)
    cudaMemsetAsync(pdeg, 0, n * sizeof(int));

    // K1: layer-1 GEMM (nodes [0, gemm_blocks_1*32)) || degree count
    gemm1_deg_k<<<gemm_blocks_1 + deg_blocks, 256>>>(
        x, W1, ph, n, gemm_blocks_1, dst, E);

    // scan -> rowptr, dinv, cursor
    scan_block_k<<<nb, SCAN_BS>>>(n);
    add_off_k<<<nb, SCAN_BS>>>(n, E);

    // K2: edge placement || layer-1 GEMM (remaining nodes)
    place_gemm1b_k<<<place_blocks + gemm_blocks_2, 256>>>(
        src, dst, E, place_blocks, x, W1, ph, n, gemm_blocks_1);

    // a1 = A_hat h1 + b1 (pair layout)
    aggregate64_k<<<cdiv((long long)n * 32, 256), 256>>>(ph, b1, pagg, n);

    // h2 = relu(a1) @ W2 (reuse g_h)
    gemm64x32_k<<<cdiv(n, 64), 256>>>(pagg, W2, ph, n);

    // fused layer-2 agg + relu + layer-3 GEMM -> h3 (reuse g_agg)
    agg32_mm2_k<<<cdiv((long long)n * 32, 256), 256>>>(ph, b2, W3, pagg, n);

    // final aggregation -> out
    aggregate2_k<<<cdiv((long long)n * 32, 256), 256>>>(pagg, b3, out, n);
}